// round 5
// baseline (speedup 1.0000x reference)
#include <cuda_runtime.h>
#include <math.h>
#include <stdint.h>

#define BB 8
#define NINST 16384
#define DM 512
#define CC 2
#define GG 8
#define KK 4
#define BUFN 1024
#define DA 128
#define MROWS (BB*NINST)      /* 131072 */
#define MG 2048               /* instances per group */
#define NGROUP (BB*GG)        /* 64 */
#define NN 1032               /* B + BUF */
#define DH 256                /* D/2 */

// ---------------- scratch (device globals; no allocation allowed) ----------
__device__ float g_mid[(size_t)MROWS * DM];      // 256 MiB
__device__ float g_score[MROWS];
__device__ float g_af[NGROUP * DM];
__device__ float g_bagfeat[BB * DM];
__device__ float g_xcat[NN * DM];
__device__ float g_xn[NN * DH];
__device__ float g_sim[NN * NN];
__device__ int   g_idx[NN * KK];
__device__ float g_h[NN * DM];
__device__ float g_m1[NN * DM];
__device__ float g_h1[NN * DM];
__device__ float g_m2[NN * DM];

// ---------------------------------------------------------------------------
// Stage 1: mid = relu(X @ Wdr + bdr). M=131072, N=512, K=512.
// 128x128 CTA tile, 16 K-tile, 256 threads, 8x8 microtile.
// ---------------------------------------------------------------------------
__global__ __launch_bounds__(256) void gemm_relu_k(
    const float* __restrict__ A, const float* __restrict__ W,
    const float* __restrict__ bias)
{
    __shared__ float As[16][136];   // A tile transposed: As[k][row], padded
    __shared__ float Bs[16][128];
    const int tid = threadIdx.x;
    const int tx = tid & 15, ty = tid >> 4;
    const int bm = blockIdx.y * 128;
    const int bn = blockIdx.x * 128;

    float acc[8][8];
#pragma unroll
    for (int i = 0; i < 8; i++)
#pragma unroll
        for (int j = 0; j < 8; j++) acc[i][j] = 0.f;

    for (int k0 = 0; k0 < DM; k0 += 16) {
#pragma unroll
        for (int l = 0; l < 2; l++) {
            int q = tid + l * 256;            // 512 float4 loads of A tile
            int row = q >> 2, kq = (q & 3) * 4;
            float4 v = *(const float4*)(A + (size_t)(bm + row) * DM + k0 + kq);
            As[kq + 0][row] = v.x; As[kq + 1][row] = v.y;
            As[kq + 2][row] = v.z; As[kq + 3][row] = v.w;
        }
#pragma unroll
        for (int l = 0; l < 2; l++) {
            int q = tid + l * 256;            // 512 float4 loads of B tile
            int kk = q >> 5, col = (q & 31) * 4;
            *(float4*)(&Bs[kk][col]) =
                *(const float4*)(W + (size_t)(k0 + kk) * DM + bn + col);
        }
        __syncthreads();
#pragma unroll
        for (int k = 0; k < 16; k++) {
            float4 a0 = *(float4*)(&As[k][ty * 8]);
            float4 a1 = *(float4*)(&As[k][ty * 8 + 4]);
            float4 b0 = *(float4*)(&Bs[k][tx * 8]);
            float4 b1 = *(float4*)(&Bs[k][tx * 8 + 4]);
            float av[8] = {a0.x,a0.y,a0.z,a0.w,a1.x,a1.y,a1.z,a1.w};
            float bv[8] = {b0.x,b0.y,b0.z,b0.w,b1.x,b1.y,b1.z,b1.w};
#pragma unroll
            for (int i = 0; i < 8; i++)
#pragma unroll
                for (int j = 0; j < 8; j++)
                    acc[i][j] += av[i] * bv[j];
        }
        __syncthreads();
    }
#pragma unroll
    for (int i = 0; i < 8; i++) {
        int row = bm + ty * 8 + i;
#pragma unroll
        for (int j = 0; j < 8; j++) {
            float v = acc[i][j] + bias[bn + tx * 8 + j];
            acc[i][j] = v > 0.f ? v : 0.f;
        }
        *(float4*)(g_mid + (size_t)row * DM + bn + tx * 8) =
            make_float4(acc[i][0], acc[i][1], acc[i][2], acc[i][3]);
        *(float4*)(g_mid + (size_t)row * DM + bn + tx * 8 + 4) =
            make_float4(acc[i][4], acc[i][5], acc[i][6], acc[i][7]);
    }
}

// ---------------------------------------------------------------------------
// Stage 2: per-instance gated-attn score.
// score = (tanh(mid@Wv1+bv1) * sigmoid(mid@Wu1+bu1)) @ Ww1 + bw1
// 64x128 CTA tile (full DA), 256 threads, 4x8 microtile per matrix.
// ---------------------------------------------------------------------------
__global__ __launch_bounds__(256) void attn_score_k(
    const float* __restrict__ Wv, const float* __restrict__ bv,
    const float* __restrict__ Wu, const float* __restrict__ bu,
    const float* __restrict__ Ww, const float* __restrict__ bw)
{
    __shared__ float As[16][72];
    __shared__ float Bv[16][128];
    __shared__ float Bu[16][128];
    const int tid = threadIdx.x;
    const int tx = tid & 15, ty = tid >> 4;
    const int bm = blockIdx.x * 64;

    float accv[4][8], accu[4][8];
#pragma unroll
    for (int i = 0; i < 4; i++)
#pragma unroll
        for (int j = 0; j < 8; j++) { accv[i][j] = 0.f; accu[i][j] = 0.f; }

    for (int k0 = 0; k0 < DM; k0 += 16) {
        {
            int q = tid;                       // 256 float4 loads (64x16 tile)
            int row = q >> 2, kq = (q & 3) * 4;
            float4 v = *(const float4*)(g_mid + (size_t)(bm + row) * DM + k0 + kq);
            As[kq + 0][row] = v.x; As[kq + 1][row] = v.y;
            As[kq + 2][row] = v.z; As[kq + 3][row] = v.w;
        }
#pragma unroll
        for (int l = 0; l < 2; l++) {
            int q = tid + l * 256;
            int kk = q >> 5, col = (q & 31) * 4;
            *(float4*)(&Bv[kk][col]) = *(const float4*)(Wv + (size_t)(k0 + kk) * DA + col);
            *(float4*)(&Bu[kk][col]) = *(const float4*)(Wu + (size_t)(k0 + kk) * DA + col);
        }
        __syncthreads();
#pragma unroll
        for (int k = 0; k < 16; k++) {
            float a[4];
#pragma unroll
            for (int i = 0; i < 4; i++) a[i] = As[k][ty * 4 + i];
            float bvv[8], buu[8];
            *(float4*)(bvv) = *(float4*)(&Bv[k][tx * 8]);
            *(float4*)(bvv + 4) = *(float4*)(&Bv[k][tx * 8 + 4]);
            *(float4*)(buu) = *(float4*)(&Bu[k][tx * 8]);
            *(float4*)(buu + 4) = *(float4*)(&Bu[k][tx * 8 + 4]);
#pragma unroll
            for (int i = 0; i < 4; i++)
#pragma unroll
                for (int j = 0; j < 8; j++) {
                    accv[i][j] += a[i] * bvv[j];
                    accu[i][j] += a[i] * buu[j];
                }
        }
        __syncthreads();
    }
    __shared__ float red[64][17];
    float part[4] = {0.f, 0.f, 0.f, 0.f};
#pragma unroll
    for (int i = 0; i < 4; i++)
#pragma unroll
        for (int j = 0; j < 8; j++) {
            int col = tx * 8 + j;
            float v = tanhf(accv[i][j] + bv[col]);
            float u = 1.f / (1.f + expf(-(accu[i][j] + bu[col])));
            part[i] += v * u * Ww[col];
        }
#pragma unroll
    for (int i = 0; i < 4; i++) red[ty * 4 + i][tx] = part[i];
    __syncthreads();
    if (tid < 64) {
        float s = 0.f;
#pragma unroll
        for (int t = 0; t < 16; t++) s += red[tid][t];
        g_score[bm + tid] = s + bw[0];
    }
}

// ---------------------------------------------------------------------------
// Stage 3: per-group softmax over m=2048 + weighted sum of mid -> af.
// One CTA per (b,g) group, 512 threads (one column each).
// ---------------------------------------------------------------------------
__global__ __launch_bounds__(512) void group_attn_k()
{
    __shared__ float w_s[MG];
    __shared__ float red[512];
    const int tid = threadIdx.x;
    const size_t base = (size_t)blockIdx.x * MG;

    float lm = -1e30f;
    for (int i = tid; i < MG; i += 512) lm = fmaxf(lm, g_score[base + i]);
    red[tid] = lm; __syncthreads();
    for (int s = 256; s > 0; s >>= 1) {
        if (tid < s) red[tid] = fmaxf(red[tid], red[tid + s]);
        __syncthreads();
    }
    const float maxv = red[0];
    __syncthreads();

    float ls = 0.f;
    for (int i = tid; i < MG; i += 512) {
        float w = expf(g_score[base + i] - maxv);
        w_s[i] = w; ls += w;
    }
    red[tid] = ls; __syncthreads();
    for (int s = 256; s > 0; s >>= 1) {
        if (tid < s) red[tid] += red[tid + s];
        __syncthreads();
    }
    const float sumv = red[0];
    __syncthreads();

    float a0 = 0.f, a1 = 0.f, a2 = 0.f, a3 = 0.f;
    const float* mp = g_mid + base * DM + tid;
    for (int i = 0; i < MG; i += 4) {
        a0 += w_s[i + 0] * mp[(size_t)(i + 0) * DM];
        a1 += w_s[i + 1] * mp[(size_t)(i + 1) * DM];
        a2 += w_s[i + 2] * mp[(size_t)(i + 2) * DM];
        a3 += w_s[i + 3] * mp[(size_t)(i + 3) * DM];
    }
    g_af[blockIdx.x * DM + tid] = ((a0 + a1) + (a2 + a3)) / sumv;
}

// ---------------------------------------------------------------------------
// Stage 4+5: per-bag attention over groups, bag_feat, bag_pred, sub_preds.
// One CTA per bag (8 CTAs, 256 threads).
// ---------------------------------------------------------------------------
__global__ __launch_bounds__(256) void bag_k(
    const float* __restrict__ Wv2, const float* __restrict__ bv2,
    const float* __restrict__ Wu2, const float* __restrict__ bu2,
    const float* __restrict__ Ww2, const float* __restrict__ bw2,
    const float* __restrict__ Wbc, const float* __restrict__ bbc,
    const float* __restrict__ Wsc, const float* __restrict__ bsc,
    float* __restrict__ out)
{
    __shared__ float afs[GG][DM];
    __shared__ float red[128];
    __shared__ float a2s[GG];
    __shared__ float bfs[DM];
    const int tid = threadIdx.x;
    const int b = blockIdx.x;

    for (int t = tid; t < GG * DM; t += 256)
        afs[t >> 9][t & 511] = g_af[(b * GG + (t >> 9)) * DM + (t & 511)];
    __syncthreads();

    for (int g = 0; g < GG; g++) {
        float p = 0.f;
        if (tid < DA) {
            int j = tid;
            float sv = 0.f, su = 0.f;
            for (int d = 0; d < DM; d++) {
                float a = afs[g][d];
                sv += a * Wv2[d * DA + j];
                su += a * Wu2[d * DA + j];
            }
            float v = tanhf(sv + bv2[j]);
            float u = 1.f / (1.f + expf(-(su + bu2[j])));
            p = v * u * Ww2[j];
        }
        if (tid < DA) red[tid] = p;
        __syncthreads();
        for (int s = 64; s > 0; s >>= 1) {
            if (tid < s) red[tid] += red[tid + s];
            __syncthreads();
        }
        if (tid == 0) a2s[g] = red[0] + bw2[0];
        __syncthreads();
    }
    if (tid == 0) {
        float mx = -1e30f;
        for (int g = 0; g < GG; g++) mx = fmaxf(mx, a2s[g]);
        float s = 0.f;
        for (int g = 0; g < GG; g++) { float e = expf(a2s[g] - mx); a2s[g] = e; s += e; }
        for (int g = 0; g < GG; g++) a2s[g] /= s;
    }
    __syncthreads();
    for (int d = tid; d < DM; d += 256) {
        float s = 0.f;
#pragma unroll
        for (int g = 0; g < GG; g++) s += a2s[g] * afs[g][d];
        bfs[d] = s;
        g_bagfeat[b * DM + d] = s;
        g_xcat[b * DM + d] = s;
    }
    __syncthreads();
    if (tid < 2) {                  // bag_pred
        int c = tid;
        float s = 0.f;
        for (int d = 0; d < DM; d++) s += bfs[d] * Wbc[d * CC + c];
        out[b * CC + c] = s + bbc[c];
    }
    if (tid >= 32 && tid < 32 + GG * CC) {   // sub_preds_cat[g*B+b]
        int t = tid - 32;
        int g = t >> 1, c = t & 1;
        float s = 0.f;
        for (int d = 0; d < DM; d++) s += afs[g][d] * Wsc[d * CC + c];
        out[BB * CC + (g * BB + b) * CC + c] = s + bsc[c];
    }
}

// ---------------------------------------------------------------------------
__global__ void copy_reh_k(const float* __restrict__ reh)
{
    int i = blockIdx.x * 256 + threadIdx.x;
    if (i < BUFN * DM) g_xcat[BB * DM + i] = reh[i];
}

// ---------------------------------------------------------------------------
// Stage 6a: _x = leaky_relu(xcat@Wf+bf); xn = _x / (||_x|| + 1e-12).
// 8 rows per CTA, 256 threads = 256 output cols.
// ---------------------------------------------------------------------------
__global__ __launch_bounds__(256) void feat_xn_k(
    const float* __restrict__ Wf, const float* __restrict__ bf)
{
    __shared__ float xs[8][DM];
    __shared__ float red[8][260];
    const int tid = threadIdx.x;
    const int r0 = blockIdx.x * 8;

    for (int t = tid; t < 8 * DM; t += 256)
        xs[t >> 9][t & 511] = g_xcat[(r0 + (t >> 9)) * DM + (t & 511)];
    __syncthreads();

    const int j = tid;
    float acc[8];
#pragma unroll
    for (int r = 0; r < 8; r++) acc[r] = 0.f;
    for (int d = 0; d < DM; d++) {
        float w = Wf[d * DH + j];
#pragma unroll
        for (int r = 0; r < 8; r++) acc[r] += xs[r][d] * w;
    }
    float xv[8];
#pragma unroll
    for (int r = 0; r < 8; r++) {
        float v = acc[r] + bf[j];
        xv[r] = v >= 0.f ? v : 0.01f * v;
        red[r][j] = xv[r] * xv[r];
    }
    __syncthreads();
    for (int s = 128; s > 0; s >>= 1) {
        if (j < s) {
#pragma unroll
            for (int r = 0; r < 8; r++) red[r][j] += red[r][j + s];
        }
        __syncthreads();
    }
#pragma unroll
    for (int r = 0; r < 8; r++) {
        float nrm = sqrtf(red[r][0]) + 1e-12f;
        g_xn[(r0 + r) * DH + j] = xv[r] / nrm;
    }
}

// ---------------------------------------------------------------------------
// Stage 6b: sim = xn @ xn^T. 32x32 CTA tile, 2x2 per thread, K chunks of 128.
// ---------------------------------------------------------------------------
__global__ __launch_bounds__(256) void sim_k()
{
    __shared__ float Asx[32][129];
    __shared__ float Bsx[32][129];
    const int tid = threadIdx.x, tx = tid & 15, ty = tid >> 4;
    const int rb = blockIdx.y * 32, cb = blockIdx.x * 32;
    float c00 = 0.f, c01 = 0.f, c10 = 0.f, c11 = 0.f;

    for (int kc = 0; kc < DH; kc += 128) {
        for (int t = tid; t < 32 * 128; t += 256) {
            int row = t >> 7, k = t & 127;
            int gr = rb + row, gc = cb + row;
            Asx[row][k] = (gr < NN) ? g_xn[gr * DH + kc + k] : 0.f;
            Bsx[row][k] = (gc < NN) ? g_xn[gc * DH + kc + k] : 0.f;
        }
        __syncthreads();
#pragma unroll 8
        for (int k = 0; k < 128; k++) {
            float a0 = Asx[ty * 2][k],     a1 = Asx[ty * 2 + 1][k];
            float b0 = Bsx[tx * 2][k],     b1 = Bsx[tx * 2 + 1][k];
            c00 += a0 * b0; c01 += a0 * b1;
            c10 += a1 * b0; c11 += a1 * b1;
        }
        __syncthreads();
    }
    int i0 = rb + ty * 2, j0 = cb + tx * 2;
    if (i0 < NN     && j0 < NN)     g_sim[i0 * NN + j0] = c00;
    if (i0 < NN     && j0 + 1 < NN) g_sim[i0 * NN + j0 + 1] = c01;
    if (i0 + 1 < NN && j0 < NN)     g_sim[(i0 + 1) * NN + j0] = c10;
    if (i0 + 1 < NN && j0 + 1 < NN) g_sim[(i0 + 1) * NN + j0 + 1] = c11;
}

// ---------------------------------------------------------------------------
// Stage 6c: top-4 indices per row (jax.lax.top_k: ties -> lower index first).
// One warp per row.
// ---------------------------------------------------------------------------
__global__ __launch_bounds__(256) void topk_k()
{
    const int warp = threadIdx.x >> 5, lane = threadIdx.x & 31;
    const int row = blockIdx.x * 8 + warp;
    const float* sr = g_sim + (size_t)row * NN;
    int sel[4] = {-1, -1, -1, -1};
#pragma unroll
    for (int k = 0; k < 4; k++) {
        float bv = -1e30f; int bi = NN;
        for (int j = lane; j < NN; j += 32) {
            if (j == sel[0] || j == sel[1] || j == sel[2] || j == sel[3]) continue;
            float v = sr[j];
            if (v > bv || (v == bv && j < bi)) { bv = v; bi = j; }
        }
        for (int off = 16; off; off >>= 1) {
            float ov = __shfl_down_sync(0xffffffffu, bv, off);
            int   oi = __shfl_down_sync(0xffffffffu, bi, off);
            if (ov > bv || (ov == bv && oi < bi)) { bv = ov; bi = oi; }
        }
        bi = __shfl_sync(0xffffffffu, bi, 0);
        sel[k] = bi;
    }
    if (lane < 4) g_idx[row * 4 + lane] = sel[lane];
}

// ---------------------------------------------------------------------------
// Stage 6d: gather-means. mode 0: h = mean(xcat[idx]) + padded(bag_feat)
//           mode 1: m1 = mean(h[idx]); mode 2: m2 = mean(h1[idx]).
// ---------------------------------------------------------------------------
__global__ void gather_mean_k(int mode)
{
    int t = blockIdx.x * 256 + threadIdx.x;
    if (t >= NN * DM) return;
    int i = t >> 9, d = t & 511;
    const float* src = (mode == 0) ? g_xcat : (mode == 1) ? g_h : g_h1;
    float* dst = (mode == 0) ? g_h : (mode == 1) ? g_m1 : g_m2;
    const int* ip = g_idx + i * 4;
    float s = src[(size_t)ip[0] * DM + d] + src[(size_t)ip[1] * DM + d]
            + src[(size_t)ip[2] * DM + d] + src[(size_t)ip[3] * DM + d];
    s *= 0.25f;
    if (mode == 0 && i < BB) s += g_bagfeat[i * DM + d];
    dst[t] = s;
}

// ---------------------------------------------------------------------------
// Stage 6e: h1 = relu(m1@Wg1 + h@Wg1s + bg1). 8 rows per CTA, 512 cols.
// ---------------------------------------------------------------------------
__global__ __launch_bounds__(256) void dualgemm_relu_k(
    const float* __restrict__ W1, const float* __restrict__ W2,
    const float* __restrict__ bias)
{
    __shared__ float ms[8][DM];
    __shared__ float hs[8][DM];
    const int tid = threadIdx.x;
    const int r0 = blockIdx.x * 8;
    for (int t = tid; t < 8 * DM; t += 256) {
        int r = t >> 9, d = t & 511;
        ms[r][d] = g_m1[(r0 + r) * DM + d];
        hs[r][d] = g_h[(r0 + r) * DM + d];
    }
    __syncthreads();
    const int j0 = tid, j1 = tid + 256;
    float acc0[8], acc1[8];
#pragma unroll
    for (int r = 0; r < 8; r++) { acc0[r] = 0.f; acc1[r] = 0.f; }
    for (int k = 0; k < DM; k++) {
        float wa0 = W1[k * DM + j0], wa1 = W1[k * DM + j1];
        float wb0 = W2[k * DM + j0], wb1 = W2[k * DM + j1];
#pragma unroll
        for (int r = 0; r < 8; r++) {
            acc0[r] += ms[r][k] * wa0 + hs[r][k] * wb0;
            acc1[r] += ms[r][k] * wa1 + hs[r][k] * wb1;
        }
    }
#pragma unroll
    for (int r = 0; r < 8; r++) {
        float v0 = acc0[r] + bias[j0];
        float v1 = acc1[r] + bias[j1];
        g_h1[(r0 + r) * DM + j0] = v0 > 0.f ? v0 : 0.f;
        g_h1[(r0 + r) * DM + j1] = v1 > 0.f ? v1 : 0.f;
    }
}

// ---------------------------------------------------------------------------
// Stage 6f: logits_graph = (m2@Wg2 + h1@Wg2s + bg2)[:8]
// ---------------------------------------------------------------------------
__global__ void final_logits_k(
    const float* __restrict__ Wg2, const float* __restrict__ Wg2s,
    const float* __restrict__ bg2, float* __restrict__ out)
{
    int t = threadIdx.x;
    if (t < BB * CC) {
        int i = t >> 1, c = t & 1;
        float s = bg2[c];
        for (int k = 0; k < DM; k++)
            s += g_m2[i * DM + k] * Wg2[k * CC + c]
               + g_h1[i * DM + k] * Wg2s[k * CC + c];
        out[BB * CC + NGROUP * CC + i * CC + c] = s;   // offset 144
    }
}

// ---------------------------------------------------------------------------
extern "C" void kernel_launch(void* const* d_in, const int* in_sizes, int n_in,
                              void* d_out, int out_size)
{
    const float* x    = (const float*)d_in[0];
    const float* reh  = (const float*)d_in[1];
    const float* Wdr  = (const float*)d_in[2];
    const float* bdr  = (const float*)d_in[3];
    const float* Wv1  = (const float*)d_in[4];
    const float* bv1  = (const float*)d_in[5];
    const float* Wu1  = (const float*)d_in[6];
    const float* bu1  = (const float*)d_in[7];
    const float* Ww1  = (const float*)d_in[8];
    const float* bw1  = (const float*)d_in[9];
    const float* Wsc  = (const float*)d_in[10];
    const float* bsc  = (const float*)d_in[11];
    const float* Wv2  = (const float*)d_in[12];
    const float* bv2  = (const float*)d_in[13];
    const float* Wu2  = (const float*)d_in[14];
    const float* bu2  = (const float*)d_in[15];
    const float* Ww2  = (const float*)d_in[16];
    const float* bw2  = (const float*)d_in[17];
    const float* Wbc  = (const float*)d_in[18];
    const float* bbc  = (const float*)d_in[19];
    const float* Wf   = (const float*)d_in[20];
    const float* bf   = (const float*)d_in[21];
    const float* Wg1  = (const float*)d_in[22];
    const float* Wg1s = (const float*)d_in[23];
    const float* bg1  = (const float*)d_in[24];
    const float* Wg2  = (const float*)d_in[25];
    const float* Wg2s = (const float*)d_in[26];
    const float* bg2  = (const float*)d_in[27];
    float* out = (float*)d_out;

    gemm_relu_k<<<dim3(4, MROWS / 128), 256>>>(x, Wdr, bdr);
    attn_score_k<<<MROWS / 64, 256>>>(Wv1, bv1, Wu1, bu1, Ww1, bw1);
    group_attn_k<<<NGROUP, 512>>>();
    bag_k<<<BB, 256>>>(Wv2, bv2, Wu2, bu2, Ww2, bw2, Wbc, bbc, Wsc, bsc, out);
    copy_reh_k<<<(BUFN * DM) / 256, 256>>>(reh);
    feat_xn_k<<<NN / 8, 256>>>(Wf, bf);
    sim_k<<<dim3(33, 33), 256>>>();
    topk_k<<<NN / 8, 256>>>();
    gather_mean_k<<<(NN * DM) / 256, 256>>>(0);
    gather_mean_k<<<(NN * DM) / 256, 256>>>(1);
    dualgemm_relu_k<<<NN / 8, 256>>>(Wg1, Wg1s, bg1);
    gather_mean_k<<<(NN * DM) / 256, 256>>>(2);
    final_logits_k<<<1, 32>>>(Wg2, Wg2s, bg2, out);
}

// round 6
// speedup vs baseline: 1.1026x; 1.1026x over previous
#include <cuda_runtime.h>
#include <math.h>
#include <stdint.h>

#define BB 8
#define NINST 16384
#define DM 512
#define CC 2
#define GG 8
#define KK 4
#define BUFN 1024
#define DA 128
#define MROWS (BB*NINST)      /* 131072 */
#define MG 2048               /* instances per group */
#define NGROUP (BB*GG)        /* 64 */
#define NN 1032               /* B + BUF */
#define DH 256                /* D/2 */

typedef unsigned long long u64;

__device__ __forceinline__ u64 pk2(float lo, float hi) {
    u64 r; asm("mov.b64 %0,{%1,%2};" : "=l"(r) : "f"(lo), "f"(hi)); return r;
}
__device__ __forceinline__ void fma2(u64& d, u64 a, u64 b) {
    asm("fma.rn.f32x2 %0,%1,%2,%0;" : "+l"(d) : "l"(a), "l"(b));
}
__device__ __forceinline__ float2 up2(u64 v) {
    float lo, hi; asm("mov.b64 {%0,%1},%2;" : "=f"(lo), "=f"(hi) : "l"(v));
    return make_float2(lo, hi);
}

// ---------------- scratch (device globals; no allocation allowed) ----------
__device__ float g_mid[(size_t)MROWS * DM];      // 256 MiB
__device__ float g_score[MROWS];
__device__ float g_gmax[NGROUP];
__device__ float g_gsum[NGROUP];
__device__ float g_afp[NGROUP * 8 * DM];
__device__ float g_af[NGROUP * DM];
__device__ float g_a2raw[NGROUP];
__device__ float g_bagfeat[BB * DM];
__device__ float g_xcat[NN * DM];
__device__ float g_xn[NN * DH];
__device__ float g_sim[NN * NN];
__device__ int   g_idx[NN * KK];
__device__ float g_h[NN * DM];
__device__ float g_m1[NN * DM];
__device__ float g_h1[NN * DM];
__device__ float g_m2[NN * DM];

// ---------------------------------------------------------------------------
// Stage 1: mid = relu(X @ Wdr + bdr). M=131072, N=512, K=512.
// 128x128 CTA tile, 32 K-tile, 256 threads, 8x8 microtile, f32x2 FMA.
// ---------------------------------------------------------------------------
__global__ __launch_bounds__(256) void gemm_relu_k(
    const float* __restrict__ A, const float* __restrict__ W,
    const float* __restrict__ bias)
{
    __shared__ float As[32][140];   // A tile transposed: As[k][row]
    __shared__ float Bs[32][128];
    const int tid = threadIdx.x;
    const int tx = tid & 15, ty = tid >> 4;
    const int bm = blockIdx.y * 128;
    const int bn = blockIdx.x * 128;

    u64 acc[8][4];
#pragma unroll
    for (int i = 0; i < 8; i++)
#pragma unroll
        for (int j = 0; j < 4; j++) acc[i][j] = 0ull;

    for (int k0 = 0; k0 < DM; k0 += 32) {
#pragma unroll
        for (int l = 0; l < 4; l++) {
            int q = tid + l * 256;            // 1024 float4 loads of A tile
            int row = q >> 3, kq = (q & 7) * 4;
            float4 v = *(const float4*)(A + (size_t)(bm + row) * DM + k0 + kq);
            As[kq + 0][row] = v.x; As[kq + 1][row] = v.y;
            As[kq + 2][row] = v.z; As[kq + 3][row] = v.w;
        }
#pragma unroll
        for (int l = 0; l < 4; l++) {
            int q = tid + l * 256;            // 1024 float4 loads of B tile
            int kk = q >> 5, col = (q & 31) * 4;
            *(float4*)(&Bs[kk][col]) =
                *(const float4*)(W + (size_t)(k0 + kk) * DM + bn + col);
        }
        __syncthreads();
#pragma unroll
        for (int k = 0; k < 32; k++) {
            float4 a0 = *(float4*)(&As[k][ty * 8]);
            float4 a1 = *(float4*)(&As[k][ty * 8 + 4]);
            ulonglong2 b01 = *(ulonglong2*)(&Bs[k][tx * 8]);
            ulonglong2 b23 = *(ulonglong2*)(&Bs[k][tx * 8 + 4]);
            u64 ap[8] = {pk2(a0.x,a0.x), pk2(a0.y,a0.y), pk2(a0.z,a0.z), pk2(a0.w,a0.w),
                         pk2(a1.x,a1.x), pk2(a1.y,a1.y), pk2(a1.z,a1.z), pk2(a1.w,a1.w)};
#pragma unroll
            for (int i = 0; i < 8; i++) {
                fma2(acc[i][0], ap[i], b01.x);
                fma2(acc[i][1], ap[i], b01.y);
                fma2(acc[i][2], ap[i], b23.x);
                fma2(acc[i][3], ap[i], b23.y);
            }
        }
        __syncthreads();
    }
#pragma unroll
    for (int i = 0; i < 8; i++) {
        int row = bm + ty * 8 + i;
        float o[8];
#pragma unroll
        for (int jp = 0; jp < 4; jp++) {
            float2 f = up2(acc[i][jp]);
            float v0 = f.x + bias[bn + tx * 8 + jp * 2];
            float v1 = f.y + bias[bn + tx * 8 + jp * 2 + 1];
            o[jp * 2]     = v0 > 0.f ? v0 : 0.f;
            o[jp * 2 + 1] = v1 > 0.f ? v1 : 0.f;
        }
        *(float4*)(g_mid + (size_t)row * DM + bn + tx * 8) =
            make_float4(o[0], o[1], o[2], o[3]);
        *(float4*)(g_mid + (size_t)row * DM + bn + tx * 8 + 4) =
            make_float4(o[4], o[5], o[6], o[7]);
    }
}

// ---------------------------------------------------------------------------
// Stage 2: per-instance gated-attn score, f32x2 FMA.
// score = (tanh(mid@Wv1+bv1) * sigmoid(mid@Wu1+bu1)) @ Ww1 + bw1
// ---------------------------------------------------------------------------
__global__ __launch_bounds__(256) void attn_score_k(
    const float* __restrict__ Wv, const float* __restrict__ bv,
    const float* __restrict__ Wu, const float* __restrict__ bu,
    const float* __restrict__ Ww, const float* __restrict__ bw)
{
    __shared__ float As[16][76];
    __shared__ float Bv[16][128];
    __shared__ float Bu[16][128];
    const int tid = threadIdx.x;
    const int tx = tid & 15, ty = tid >> 4;
    const int bm = blockIdx.x * 64;

    u64 accv[4][4], accu[4][4];
#pragma unroll
    for (int i = 0; i < 4; i++)
#pragma unroll
        for (int j = 0; j < 4; j++) { accv[i][j] = 0ull; accu[i][j] = 0ull; }

    for (int k0 = 0; k0 < DM; k0 += 16) {
        {
            int q = tid;                       // 256 float4 loads (64x16 tile)
            int row = q >> 2, kq = (q & 3) * 4;
            float4 v = *(const float4*)(g_mid + (size_t)(bm + row) * DM + k0 + kq);
            As[kq + 0][row] = v.x; As[kq + 1][row] = v.y;
            As[kq + 2][row] = v.z; As[kq + 3][row] = v.w;
        }
#pragma unroll
        for (int l = 0; l < 2; l++) {
            int q = tid + l * 256;
            int kk = q >> 5, col = (q & 31) * 4;
            *(float4*)(&Bv[kk][col]) = *(const float4*)(Wv + (size_t)(k0 + kk) * DA + col);
            *(float4*)(&Bu[kk][col]) = *(const float4*)(Wu + (size_t)(k0 + kk) * DA + col);
        }
        __syncthreads();
#pragma unroll
        for (int k = 0; k < 16; k++) {
            u64 ap[4];
#pragma unroll
            for (int i = 0; i < 4; i++) {
                float a = As[k][ty * 4 + i];
                ap[i] = pk2(a, a);
            }
            ulonglong2 v01 = *(ulonglong2*)(&Bv[k][tx * 8]);
            ulonglong2 v23 = *(ulonglong2*)(&Bv[k][tx * 8 + 4]);
            ulonglong2 u01 = *(ulonglong2*)(&Bu[k][tx * 8]);
            ulonglong2 u23 = *(ulonglong2*)(&Bu[k][tx * 8 + 4]);
#pragma unroll
            for (int i = 0; i < 4; i++) {
                fma2(accv[i][0], ap[i], v01.x);
                fma2(accv[i][1], ap[i], v01.y);
                fma2(accv[i][2], ap[i], v23.x);
                fma2(accv[i][3], ap[i], v23.y);
                fma2(accu[i][0], ap[i], u01.x);
                fma2(accu[i][1], ap[i], u01.y);
                fma2(accu[i][2], ap[i], u23.x);
                fma2(accu[i][3], ap[i], u23.y);
            }
        }
        __syncthreads();
    }
    __shared__ float red[64][17];
    float part[4] = {0.f, 0.f, 0.f, 0.f};
#pragma unroll
    for (int i = 0; i < 4; i++)
#pragma unroll
        for (int jp = 0; jp < 4; jp++) {
            float2 fv = up2(accv[i][jp]);
            float2 fu = up2(accu[i][jp]);
            int c0 = tx * 8 + jp * 2, c1 = c0 + 1;
            float v0 = tanhf(fv.x + bv[c0]);
            float u0 = 1.f / (1.f + expf(-(fu.x + bu[c0])));
            part[i] += v0 * u0 * Ww[c0];
            float v1 = tanhf(fv.y + bv[c1]);
            float u1 = 1.f / (1.f + expf(-(fu.y + bu[c1])));
            part[i] += v1 * u1 * Ww[c1];
        }
#pragma unroll
    for (int i = 0; i < 4; i++) red[ty * 4 + i][tx] = part[i];
    __syncthreads();
    if (tid < 64) {
        float s = 0.f;
#pragma unroll
        for (int t = 0; t < 16; t++) s += red[tid][t];
        g_score[bm + tid] = s + bw[0];
    }
}

// ---------------------------------------------------------------------------
// Stage 3a: per-group softmax stats (max + sum of exp).
// ---------------------------------------------------------------------------
__global__ __launch_bounds__(256) void softmax_stats_k()
{
    __shared__ float red[256];
    const int tid = threadIdx.x;
    const size_t base = (size_t)blockIdx.x * MG;

    float lm = -1e30f;
    for (int i = tid; i < MG; i += 256) lm = fmaxf(lm, g_score[base + i]);
    red[tid] = lm; __syncthreads();
    for (int s = 128; s > 0; s >>= 1) {
        if (tid < s) red[tid] = fmaxf(red[tid], red[tid + s]);
        __syncthreads();
    }
    const float maxv = red[0];
    __syncthreads();

    float ls = 0.f;
    for (int i = tid; i < MG; i += 256) ls += expf(g_score[base + i] - maxv);
    red[tid] = ls; __syncthreads();
    for (int s = 128; s > 0; s >>= 1) {
        if (tid < s) red[tid] += red[tid + s];
        __syncthreads();
    }
    if (tid == 0) { g_gmax[blockIdx.x] = maxv; g_gsum[blockIdx.x] = red[0]; }
}

// ---------------------------------------------------------------------------
// Stage 3b: weighted partial sums of mid (8 chunks of 256 rows per group).
// ---------------------------------------------------------------------------
__global__ __launch_bounds__(512) void weighted_partial_k()
{
    __shared__ float w_s[256];
    const int tid = threadIdx.x;
    const int chunk = blockIdx.x, g = blockIdx.y;
    const size_t base = (size_t)g * MG + chunk * 256;
    const float maxv = g_gmax[g];

    if (tid < 256) w_s[tid] = expf(g_score[base + tid] - maxv);
    __syncthreads();

    float a0 = 0.f, a1 = 0.f, a2 = 0.f, a3 = 0.f;
    const float* mp = g_mid + base * DM + tid;
    for (int i = 0; i < 256; i += 4) {
        a0 += w_s[i + 0] * mp[(size_t)(i + 0) * DM];
        a1 += w_s[i + 1] * mp[(size_t)(i + 1) * DM];
        a2 += w_s[i + 2] * mp[(size_t)(i + 2) * DM];
        a3 += w_s[i + 3] * mp[(size_t)(i + 3) * DM];
    }
    g_afp[(g * 8 + chunk) * DM + tid] = ((a0 + a1) + (a2 + a3));
}

// ---------------------------------------------------------------------------
// Stage 3c: reduce partials -> af.
// ---------------------------------------------------------------------------
__global__ __launch_bounds__(512) void af_reduce_k()
{
    const int g = blockIdx.x, d = threadIdx.x;
    float s = 0.f;
#pragma unroll
    for (int c = 0; c < 8; c++) s += g_afp[(g * 8 + c) * DM + d];
    g_af[g * DM + d] = s / g_gsum[g];
}

// ---------------------------------------------------------------------------
// Stage 4a: per-group gated-attn raw score (64 CTAs, 128 threads).
// ---------------------------------------------------------------------------
__global__ __launch_bounds__(128) void bag_score_k(
    const float* __restrict__ Wv2, const float* __restrict__ bv2,
    const float* __restrict__ Wu2, const float* __restrict__ bu2,
    const float* __restrict__ Ww2, const float* __restrict__ bw2)
{
    __shared__ float afs[DM];
    __shared__ float red[128];
    const int tid = threadIdx.x;
    const int g = blockIdx.x;
    for (int t = tid; t < DM; t += 128) afs[t] = g_af[g * DM + t];
    __syncthreads();

    const int j = tid;
    float sv = 0.f, su = 0.f;
#pragma unroll 4
    for (int d = 0; d < DM; d++) {
        float a = afs[d];
        sv += a * Wv2[d * DA + j];
        su += a * Wu2[d * DA + j];
    }
    float v = tanhf(sv + bv2[j]);
    float u = 1.f / (1.f + expf(-(su + bu2[j])));
    red[tid] = v * u * Ww2[j];
    __syncthreads();
    for (int s = 64; s > 0; s >>= 1) {
        if (tid < s) red[tid] += red[tid + s];
        __syncthreads();
    }
    if (tid == 0) g_a2raw[g] = red[0] + bw2[0];
}

// ---------------------------------------------------------------------------
// Stage 5a: sub_preds_cat (64 CTAs, 128 threads).
// ---------------------------------------------------------------------------
__global__ __launch_bounds__(128) void subpred_k(
    const float* __restrict__ Wsc, const float* __restrict__ bsc,
    float* __restrict__ out)
{
    __shared__ float afs[DM];
    __shared__ float red[128];
    const int tid = threadIdx.x;
    const int gi = blockIdx.x;            // = b*GG + gl
    for (int t = tid; t < DM; t += 128) afs[t] = g_af[gi * DM + t];
    __syncthreads();
    const int c = tid & 1, lane = tid >> 1;   // 64 lanes per class
    float s = 0.f;
    for (int d = lane; d < DM; d += 64) s += afs[d] * Wsc[d * CC + c];
    red[c * 64 + lane] = s;
    __syncthreads();
    for (int st = 32; st > 0; st >>= 1) {
        if (lane < st) red[c * 64 + lane] += red[c * 64 + lane + st];
        __syncthreads();
    }
    if (lane == 0) {
        int b = gi >> 3, gl = gi & 7;
        out[BB * CC + (gl * BB + b) * CC + c] = red[c * 64] + bsc[c];
    }
}

// ---------------------------------------------------------------------------
// Stage 4b+5b: per-bag softmax over groups, bag_feat, bag_pred.
// ---------------------------------------------------------------------------
__global__ __launch_bounds__(256) void bag_final_k(
    const float* __restrict__ Wbc, const float* __restrict__ bbc,
    float* __restrict__ out)
{
    __shared__ float afs[GG][DM];
    __shared__ float w[GG];
    __shared__ float bfs[DM];
    __shared__ float red[256];
    const int tid = threadIdx.x;
    const int b = blockIdx.x;

    for (int t = tid; t < GG * DM; t += 256)
        afs[t >> 9][t & 511] = g_af[(b * GG + (t >> 9)) * DM + (t & 511)];
    if (tid == 0) {
        float a2[GG], mx = -1e30f;
        for (int g = 0; g < GG; g++) { a2[g] = g_a2raw[b * GG + g]; mx = fmaxf(mx, a2[g]); }
        float s = 0.f;
        for (int g = 0; g < GG; g++) { a2[g] = expf(a2[g] - mx); s += a2[g]; }
        for (int g = 0; g < GG; g++) w[g] = a2[g] / s;
    }
    __syncthreads();
    for (int d = tid; d < DM; d += 256) {
        float s = 0.f;
#pragma unroll
        for (int g = 0; g < GG; g++) s += w[g] * afs[g][d];
        bfs[d] = s;
        g_bagfeat[b * DM + d] = s;
        g_xcat[b * DM + d] = s;
    }
    __syncthreads();
    const int c = tid & 1, lane = tid >> 1;   // 128 lanes per class
    float s = 0.f;
    for (int d = lane; d < DM; d += 128) s += bfs[d] * Wbc[d * CC + c];
    red[c * 128 + lane] = s;
    __syncthreads();
    for (int st = 64; st > 0; st >>= 1) {
        if (lane < st) red[c * 128 + lane] += red[c * 128 + lane + st];
        __syncthreads();
    }
    if (lane == 0) out[b * CC + c] = red[c * 128] + bbc[c];
}

// ---------------------------------------------------------------------------
__global__ void copy_reh_k(const float* __restrict__ reh)
{
    int i = blockIdx.x * 256 + threadIdx.x;
    *(float4*)(g_xcat + BB * DM + i * 4) = *(const float4*)(reh + i * 4);
}

// ---------------------------------------------------------------------------
// Stage 6a: _x = leaky_relu(xcat@Wf+bf); xn = _x / (||_x|| + 1e-12).
// ---------------------------------------------------------------------------
__global__ __launch_bounds__(256) void feat_xn_k(
    const float* __restrict__ Wf, const float* __restrict__ bf)
{
    __shared__ float xs[8][DM];
    __shared__ float red[8][260];
    const int tid = threadIdx.x;
    const int r0 = blockIdx.x * 8;

    for (int t = tid; t < 8 * DM; t += 256)
        xs[t >> 9][t & 511] = g_xcat[(r0 + (t >> 9)) * DM + (t & 511)];
    __syncthreads();

    const int j = tid;
    float acc[8];
#pragma unroll
    for (int r = 0; r < 8; r++) acc[r] = 0.f;
    for (int d = 0; d < DM; d++) {
        float w = Wf[d * DH + j];
#pragma unroll
        for (int r = 0; r < 8; r++) acc[r] += xs[r][d] * w;
    }
    float xv[8];
#pragma unroll
    for (int r = 0; r < 8; r++) {
        float v = acc[r] + bf[j];
        xv[r] = v >= 0.f ? v : 0.01f * v;
        red[r][j] = xv[r] * xv[r];
    }
    __syncthreads();
    for (int s = 128; s > 0; s >>= 1) {
        if (j < s) {
#pragma unroll
            for (int r = 0; r < 8; r++) red[r][j] += red[r][j + s];
        }
        __syncthreads();
    }
#pragma unroll
    for (int r = 0; r < 8; r++) {
        float nrm = sqrtf(red[r][0]) + 1e-12f;
        g_xn[(r0 + r) * DH + j] = xv[r] / nrm;
    }
}

// ---------------------------------------------------------------------------
// Stage 6b: sim = xn @ xn^T.
// ---------------------------------------------------------------------------
__global__ __launch_bounds__(256) void sim_k()
{
    __shared__ float Asx[32][129];
    __shared__ float Bsx[32][129];
    const int tid = threadIdx.x, tx = tid & 15, ty = tid >> 4;
    const int rb = blockIdx.y * 32, cb = blockIdx.x * 32;
    float c00 = 0.f, c01 = 0.f, c10 = 0.f, c11 = 0.f;

    for (int kc = 0; kc < DH; kc += 128) {
        for (int t = tid; t < 32 * 128; t += 256) {
            int row = t >> 7, k = t & 127;
            int gr = rb + row, gc = cb + row;
            Asx[row][k] = (gr < NN) ? g_xn[gr * DH + kc + k] : 0.f;
            Bsx[row][k] = (gc < NN) ? g_xn[gc * DH + kc + k] : 0.f;
        }
        __syncthreads();
#pragma unroll 8
        for (int k = 0; k < 128; k++) {
            float a0 = Asx[ty * 2][k],     a1 = Asx[ty * 2 + 1][k];
            float b0 = Bsx[tx * 2][k],     b1 = Bsx[tx * 2 + 1][k];
            c00 += a0 * b0; c01 += a0 * b1;
            c10 += a1 * b0; c11 += a1 * b1;
        }
        __syncthreads();
    }
    int i0 = rb + ty * 2, j0 = cb + tx * 2;
    if (i0 < NN     && j0 < NN)     g_sim[i0 * NN + j0] = c00;
    if (i0 < NN     && j0 + 1 < NN) g_sim[i0 * NN + j0 + 1] = c01;
    if (i0 + 1 < NN && j0 < NN)     g_sim[(i0 + 1) * NN + j0] = c10;
    if (i0 + 1 < NN && j0 + 1 < NN) g_sim[(i0 + 1) * NN + j0 + 1] = c11;
}

// ---------------------------------------------------------------------------
// Stage 6c: top-4 indices per row (ties -> lower index first).
// ---------------------------------------------------------------------------
__global__ __launch_bounds__(256) void topk_k()
{
    const int warp = threadIdx.x >> 5, lane = threadIdx.x & 31;
    const int row = blockIdx.x * 8 + warp;
    const float* sr = g_sim + (size_t)row * NN;
    int sel[4] = {-1, -1, -1, -1};
#pragma unroll
    for (int k = 0; k < 4; k++) {
        float bv = -1e30f; int bi = NN;
        for (int j = lane; j < NN; j += 32) {
            if (j == sel[0] || j == sel[1] || j == sel[2] || j == sel[3]) continue;
            float v = sr[j];
            if (v > bv || (v == bv && j < bi)) { bv = v; bi = j; }
        }
        for (int off = 16; off; off >>= 1) {
            float ov = __shfl_down_sync(0xffffffffu, bv, off);
            int   oi = __shfl_down_sync(0xffffffffu, bi, off);
            if (ov > bv || (ov == bv && oi < bi)) { bv = ov; bi = oi; }
        }
        bi = __shfl_sync(0xffffffffu, bi, 0);
        sel[k] = bi;
    }
    if (lane < 4) g_idx[row * 4 + lane] = sel[lane];
}

// ---------------------------------------------------------------------------
// Stage 6d: gather-means (float4 vectorized).
// ---------------------------------------------------------------------------
__global__ void gather_mean_k(int mode)
{
    int t = blockIdx.x * 256 + threadIdx.x;      // over NN*DM/4
    if (t >= NN * DM / 4) return;
    int i = t >> 7, d4 = (t & 127) * 4;
    const float* src = (mode == 0) ? g_xcat : (mode == 1) ? g_h : g_h1;
    float* dst = (mode == 0) ? g_h : (mode == 1) ? g_m1 : g_m2;
    const int* ip = g_idx + i * 4;
    float4 s0 = *(const float4*)(src + (size_t)ip[0] * DM + d4);
    float4 s1 = *(const float4*)(src + (size_t)ip[1] * DM + d4);
    float4 s2 = *(const float4*)(src + (size_t)ip[2] * DM + d4);
    float4 s3 = *(const float4*)(src + (size_t)ip[3] * DM + d4);
    float4 r;
    r.x = (s0.x + s1.x + s2.x + s3.x) * 0.25f;
    r.y = (s0.y + s1.y + s2.y + s3.y) * 0.25f;
    r.z = (s0.z + s1.z + s2.z + s3.z) * 0.25f;
    r.w = (s0.w + s1.w + s2.w + s3.w) * 0.25f;
    if (mode == 0 && i < BB) {
        float4 bfv = *(const float4*)(g_bagfeat + i * DM + d4);
        r.x += bfv.x; r.y += bfv.y; r.z += bfv.z; r.w += bfv.w;
    }
    *(float4*)(dst + (size_t)i * DM + d4) = r;
}

// ---------------------------------------------------------------------------
// Stage 6e: h1 = relu(m1@Wg1 + h@Wg1s + bg1). f32x2, col-pair per thread.
// ---------------------------------------------------------------------------
__global__ __launch_bounds__(256) void dualgemm_relu_k(
    const float* __restrict__ W1, const float* __restrict__ W2,
    const float* __restrict__ bias)
{
    __shared__ float ms[8][DM];
    __shared__ float hs[8][DM];
    const int tid = threadIdx.x;
    const int r0 = blockIdx.x * 8;
    for (int t = tid; t < 8 * DM; t += 256) {
        int r = t >> 9, d = t & 511;
        ms[r][d] = g_m1[(r0 + r) * DM + d];
        hs[r][d] = g_h[(r0 + r) * DM + d];
    }
    __syncthreads();
    const int j = 2 * tid;
    u64 acc[8];
#pragma unroll
    for (int r = 0; r < 8; r++) acc[r] = 0ull;
#pragma unroll 4
    for (int k = 0; k < DM; k++) {
        u64 wa = *(const u64*)(W1 + (size_t)k * DM + j);
        u64 wb = *(const u64*)(W2 + (size_t)k * DM + j);
#pragma unroll
        for (int r = 0; r < 8; r++) {
            float m = ms[r][k], h = hs[r][k];
            fma2(acc[r], pk2(m, m), wa);
            fma2(acc[r], pk2(h, h), wb);
        }
    }
#pragma unroll
    for (int r = 0; r < 8; r++) {
        float2 f = up2(acc[r]);
        float v0 = f.x + bias[j];
        float v1 = f.y + bias[j + 1];
        g_h1[(r0 + r) * DM + j]     = v0 > 0.f ? v0 : 0.f;
        g_h1[(r0 + r) * DM + j + 1] = v1 > 0.f ? v1 : 0.f;
    }
}

// ---------------------------------------------------------------------------
// Stage 6f: logits_graph = (m2@Wg2 + h1@Wg2s + bg2)[:8]
// ---------------------------------------------------------------------------
__global__ void final_logits_k(
    const float* __restrict__ Wg2, const float* __restrict__ Wg2s,
    const float* __restrict__ bg2, float* __restrict__ out)
{
    int t = threadIdx.x;
    if (t < BB * CC) {
        int i = t >> 1, c = t & 1;
        float s = bg2[c];
        for (int k = 0; k < DM; k++)
            s += g_m2[i * DM + k] * Wg2[k * CC + c]
               + g_h1[i * DM + k] * Wg2s[k * CC + c];
        out[BB * CC + NGROUP * CC + i * CC + c] = s;   // offset 144
    }
}

// ---------------------------------------------------------------------------
extern "C" void kernel_launch(void* const* d_in, const int* in_sizes, int n_in,
                              void* d_out, int out_size)
{
    const float* x    = (const float*)d_in[0];
    const float* reh  = (const float*)d_in[1];
    const float* Wdr  = (const float*)d_in[2];
    const float* bdr  = (const float*)d_in[3];
    const float* Wv1  = (const float*)d_in[4];
    const float* bv1  = (const float*)d_in[5];
    const float* Wu1  = (const float*)d_in[6];
    const float* bu1  = (const float*)d_in[7];
    const float* Ww1  = (const float*)d_in[8];
    const float* bw1  = (const float*)d_in[9];
    const float* Wsc  = (const float*)d_in[10];
    const float* bsc  = (const float*)d_in[11];
    const float* Wv2  = (const float*)d_in[12];
    const float* bv2  = (const float*)d_in[13];
    const float* Wu2  = (const float*)d_in[14];
    const float* bu2  = (const float*)d_in[15];
    const float* Ww2  = (const float*)d_in[16];
    const float* bw2  = (const float*)d_in[17];
    const float* Wbc  = (const float*)d_in[18];
    const float* bbc  = (const float*)d_in[19];
    const float* Wf   = (const float*)d_in[20];
    const float* bf   = (const float*)d_in[21];
    const float* Wg1  = (const float*)d_in[22];
    const float* Wg1s = (const float*)d_in[23];
    const float* bg1  = (const float*)d_in[24];
    const float* Wg2  = (const float*)d_in[25];
    const float* Wg2s = (const float*)d_in[26];
    const float* bg2  = (const float*)d_in[27];
    float* out = (float*)d_out;

    gemm_relu_k<<<dim3(4, MROWS / 128), 256>>>(x, Wdr, bdr);
    attn_score_k<<<MROWS / 64, 256>>>(Wv1, bv1, Wu1, bu1, Ww1, bw1);
    softmax_stats_k<<<NGROUP, 256>>>();
    weighted_partial_k<<<dim3(8, NGROUP), 512>>>();
    af_reduce_k<<<NGROUP, 512>>>();
    bag_score_k<<<NGROUP, 128>>>(Wv2, bv2, Wu2, bu2, Ww2, bw2);
    subpred_k<<<NGROUP, 128>>>(Wsc, bsc, out);
    bag_final_k<<<BB, 256>>>(Wbc, bbc, out);
    copy_reh_k<<<(BUFN * DM / 4) / 256, 256>>>(reh);
    feat_xn_k<<<NN / 8, 256>>>(Wf, bf);
    sim_k<<<dim3(33, 33), 256>>>();
    topk_k<<<NN / 8, 256>>>();
    gather_mean_k<<<(NN * DM / 4 + 255) / 256, 256>>>(0);
    gather_mean_k<<<(NN * DM / 4 + 255) / 256, 256>>>(1);
    dualgemm_relu_k<<<NN / 8, 256>>>(Wg1, Wg1s, bg1);
    gather_mean_k<<<(NN * DM / 4 + 255) / 256, 256>>>(2);
    final_logits_k<<<1, 32>>>(Wg2, Wg2s, bg2, out);
}

// round 7
// speedup vs baseline: 1.3175x; 1.1949x over previous
#include <cuda_runtime.h>
#include <cuda_bf16.h>
#include <math.h>
#include <stdint.h>

#define BB 8
#define NINST 16384
#define DM 512
#define CC 2
#define GG 8
#define KK 4
#define BUFN 1024
#define DA 128
#define MROWS (BB*NINST)      /* 131072 */
#define MG 2048               /* instances per group */
#define NGROUP (BB*GG)        /* 64 */
#define NN 1032               /* B + BUF */
#define DH 256                /* D/2 */

typedef unsigned long long u64;

__device__ __forceinline__ u64 pk2(float lo, float hi) {
    u64 r; asm("mov.b64 %0,{%1,%2};" : "=l"(r) : "f"(lo), "f"(hi)); return r;
}
__device__ __forceinline__ void fma2(u64& d, u64 a, u64 b) {
    asm("fma.rn.f32x2 %0,%1,%2,%0;" : "+l"(d) : "l"(a), "l"(b));
}
__device__ __forceinline__ float2 up2(u64 v) {
    float lo, hi; asm("mov.b64 {%0,%1},%2;" : "=f"(lo), "=f"(hi) : "l"(v));
    return make_float2(lo, hi);
}

// bf16 split: (x,y) -> hi bf16x2 + lo bf16x2 (residual), 3-term GEMM accuracy ~1e-5
__device__ __forceinline__ void split2(float x, float y, unsigned &hi, unsigned &lo)
{
    __nv_bfloat162 h = __floats2bfloat162_rn(x, y);
    float2 hf = __bfloat1622float2(h);
    __nv_bfloat162 l = __floats2bfloat162_rn(x - hf.x, y - hf.y);
    hi = *reinterpret_cast<unsigned*>(&h);
    lo = *reinterpret_cast<unsigned*>(&l);
}

__device__ __forceinline__ void mma16816(float* c,
    unsigned a0, unsigned a1, unsigned a2, unsigned a3,
    unsigned b0, unsigned b1)
{
    asm volatile("mma.sync.aligned.m16n8k16.row.col.f32.bf16.bf16.f32 "
        "{%0,%1,%2,%3},{%4,%5,%6,%7},{%8,%9},{%0,%1,%2,%3};"
        : "+f"(c[0]), "+f"(c[1]), "+f"(c[2]), "+f"(c[3])
        : "r"(a0), "r"(a1), "r"(a2), "r"(a3), "r"(b0), "r"(b1));
}

__device__ __forceinline__ float tanh_fast(float x) {
    float e = __expf(2.f * x);
    return 1.f - __fdividef(2.f, e + 1.f);
}
__device__ __forceinline__ float sigm_fast(float x) {
    return __fdividef(1.f, 1.f + __expf(-x));
}

// ---------------- scratch (device globals; no allocation allowed) ----------
__device__ float g_mid[(size_t)MROWS * DM];      // 256 MiB
__device__ float g_score[MROWS];
__device__ float g_gmax[NGROUP];
__device__ float g_gsum[NGROUP];
__device__ float g_afp[NGROUP * 8 * DM];
__device__ float g_af[NGROUP * DM];
__device__ float g_a2raw[NGROUP];
__device__ float g_bagfeat[BB * DM];
__device__ float g_xcat[NN * DM];
__device__ float g_xn[NN * DH];
__device__ float g_sim[NN * NN];
__device__ int   g_idx[NN * KK];
__device__ float g_h[NN * DM];
__device__ float g_m1[NN * DM];
__device__ float g_h1[NN * DM];
__device__ float g_m2[NN * DM];

// ---------------------------------------------------------------------------
// Stage 1 (tensor cores): mid = relu(X @ Wdr + bdr). M=131072, N=512, K=512.
// CTA 128x128, 8 warps (4m x 2n), warp tile 32x64, k-tile 32, bf16 3-term split.
// Smem: hi/lo packed as uint2 (.x = hi bf16x2, .y = lo bf16x2), k-pair indexed.
// ---------------------------------------------------------------------------
__global__ __launch_bounds__(256) void gemm_relu_tc(
    const float* __restrict__ A, const float* __restrict__ W,
    const float* __restrict__ bias)
{
    __shared__ uint2 As[128][20];    // [row][kpair], stride 20 -> conflict-free
    __shared__ uint2 Bs[16][132];    // [kpair][n],  stride 132 -> conflict-free
    const int tid = threadIdx.x, lane = tid & 31, wid = tid >> 5;
    const int wm = wid & 3, wn = wid >> 2;
    const int bm = blockIdx.y * 128, bn = blockIdx.x * 128;

    float c[2][8][4];
#pragma unroll
    for (int i = 0; i < 2; i++)
#pragma unroll
        for (int j = 0; j < 8; j++)
#pragma unroll
            for (int q = 0; q < 4; q++) c[i][j][q] = 0.f;

    for (int k0 = 0; k0 < DM; k0 += 32) {
        // ---- fill A tile: 128 rows x 32 k
#pragma unroll
        for (int l = 0; l < 4; l++) {
            int q = tid + l * 256;
            int row = q >> 3, kq = (q & 7) * 4;
            float4 v = *(const float4*)(A + (size_t)(bm + row) * DM + k0 + kq);
            unsigned h0, l0, h1, l1;
            split2(v.x, v.y, h0, l0);
            split2(v.z, v.w, h1, l1);
            uint4 pack = make_uint4(h0, l0, h1, l1);
            *(uint4*)(&As[row][kq >> 1]) = pack;
        }
        // ---- fill B tile: 16 kpairs x 128 cols
#pragma unroll
        for (int l = 0; l < 2; l++) {
            int q = tid + l * 256;
            int kp = q >> 5, col = (q & 31) * 4;
            const float* w0 = W + (size_t)(k0 + 2 * kp) * DM + bn + col;
            float4 r0 = *(const float4*)w0;
            float4 r1 = *(const float4*)(w0 + DM);
            unsigned h, lo;
            split2(r0.x, r1.x, h, lo); Bs[kp][col]     = make_uint2(h, lo);
            split2(r0.y, r1.y, h, lo); Bs[kp][col + 1] = make_uint2(h, lo);
            split2(r0.z, r1.z, h, lo); Bs[kp][col + 2] = make_uint2(h, lo);
            split2(r0.w, r1.w, h, lo); Bs[kp][col + 3] = make_uint2(h, lo);
        }
        __syncthreads();
#pragma unroll
        for (int st = 0; st < 2; st++) {
            const int kb = st * 8 + (lane & 3);
            uint2 a0[2], a1[2], a2[2], a3[2];
#pragma unroll
            for (int tm = 0; tm < 2; tm++) {
                int r = wm * 32 + tm * 16 + (lane >> 2);
                a0[tm] = As[r][kb];     a1[tm] = As[r + 8][kb];
                a2[tm] = As[r][kb + 4]; a3[tm] = As[r + 8][kb + 4];
            }
#pragma unroll
            for (int tn = 0; tn < 8; tn++) {
                int n = wn * 64 + tn * 8 + (lane >> 2);
                uint2 b0 = Bs[kb][n], b1 = Bs[kb + 4][n];
#pragma unroll
                for (int tm = 0; tm < 2; tm++) {
                    mma16816(c[tm][tn], a0[tm].x, a1[tm].x, a2[tm].x, a3[tm].x, b0.x, b1.x);
                    mma16816(c[tm][tn], a0[tm].x, a1[tm].x, a2[tm].x, a3[tm].x, b0.y, b1.y);
                    mma16816(c[tm][tn], a0[tm].y, a1[tm].y, a2[tm].y, a3[tm].y, b0.x, b1.x);
                }
            }
        }
        __syncthreads();
    }
#pragma unroll
    for (int tm = 0; tm < 2; tm++) {
        int row = bm + wm * 32 + tm * 16 + (lane >> 2);
#pragma unroll
        for (int tn = 0; tn < 8; tn++) {
            int col = bn + wn * 64 + tn * 8 + (lane & 3) * 2;
            float b0 = bias[col], b1 = bias[col + 1];
            float v0 = c[tm][tn][0] + b0; v0 = v0 > 0.f ? v0 : 0.f;
            float v1 = c[tm][tn][1] + b1; v1 = v1 > 0.f ? v1 : 0.f;
            float v2 = c[tm][tn][2] + b0; v2 = v2 > 0.f ? v2 : 0.f;
            float v3 = c[tm][tn][3] + b1; v3 = v3 > 0.f ? v3 : 0.f;
            *(float2*)(g_mid + (size_t)row * DM + col)       = make_float2(v0, v1);
            *(float2*)(g_mid + (size_t)(row + 8) * DM + col) = make_float2(v2, v3);
        }
    }
}

// ---------------------------------------------------------------------------
// Stage 2 (tensor cores): gated-attn score.
// One GEMM 64x256 per CTA (Wv/Wu column-interleaved: even n=V, odd n=U), then
// tanh*sigmoid*Ww epilogue with quad shuffles + cross-warp reduction.
// 8 warps (2m x 4n), warp tile 32x64, k-tile 32.
// ---------------------------------------------------------------------------
__global__ __launch_bounds__(256) void attn_score_tc(
    const float* __restrict__ Wv, const float* __restrict__ bv,
    const float* __restrict__ Wu, const float* __restrict__ bu,
    const float* __restrict__ Ww, const float* __restrict__ bw)
{
    __shared__ uint2 As[64][20];
    __shared__ uint2 Bs[16][260];   // [kpair][n interleaved 0..255]
    __shared__ float red[64][5];
    const int tid = threadIdx.x, lane = tid & 31, wid = tid >> 5;
    const int wm = wid & 1, wn = wid >> 1;
    const int bm = blockIdx.x * 64;

    float c[2][8][4];
#pragma unroll
    for (int i = 0; i < 2; i++)
#pragma unroll
        for (int j = 0; j < 8; j++)
#pragma unroll
            for (int q = 0; q < 4; q++) c[i][j][q] = 0.f;

    for (int k0 = 0; k0 < DM; k0 += 32) {
        // ---- fill A tile: 64 rows x 32 k from g_mid
#pragma unroll
        for (int l = 0; l < 2; l++) {
            int q = tid + l * 256;
            int row = q >> 3, kq = (q & 7) * 4;
            float4 v = *(const float4*)(g_mid + (size_t)(bm + row) * DM + k0 + kq);
            unsigned h0, l0, h1, l1;
            split2(v.x, v.y, h0, l0);
            split2(v.z, v.w, h1, l1);
            *(uint4*)(&As[row][kq >> 1]) = make_uint4(h0, l0, h1, l1);
        }
        // ---- fill B tile interleaved: [kp][2j] = Wv col j, [kp][2j+1] = Wu col j
#pragma unroll
        for (int l = 0; l < 8; l++) {
            int q = tid + l * 256;       // 2048 tasks: 16 kp x 128 j
            int kp = q >> 7, j = q & 127;
            const float* pv = Wv + (size_t)(k0 + 2 * kp) * DA + j;
            const float* pu = Wu + (size_t)(k0 + 2 * kp) * DA + j;
            unsigned vh, vl, uh, ul;
            split2(pv[0], pv[DA], vh, vl);
            split2(pu[0], pu[DA], uh, ul);
            *(uint4*)(&Bs[kp][2 * j]) = make_uint4(vh, vl, uh, ul);
        }
        __syncthreads();
#pragma unroll
        for (int st = 0; st < 2; st++) {
            const int kb = st * 8 + (lane & 3);
            uint2 a0[2], a1[2], a2[2], a3[2];
#pragma unroll
            for (int tm = 0; tm < 2; tm++) {
                int r = wm * 32 + tm * 16 + (lane >> 2);
                a0[tm] = As[r][kb];     a1[tm] = As[r + 8][kb];
                a2[tm] = As[r][kb + 4]; a3[tm] = As[r + 8][kb + 4];
            }
#pragma unroll
            for (int tn = 0; tn < 8; tn++) {
                int n = wn * 64 + tn * 8 + (lane >> 2);
                uint2 b0 = Bs[kb][n], b1 = Bs[kb + 4][n];
#pragma unroll
                for (int tm = 0; tm < 2; tm++) {
                    mma16816(c[tm][tn], a0[tm].x, a1[tm].x, a2[tm].x, a3[tm].x, b0.x, b1.x);
                    mma16816(c[tm][tn], a0[tm].x, a1[tm].x, a2[tm].x, a3[tm].x, b0.y, b1.y);
                    mma16816(c[tm][tn], a0[tm].y, a1[tm].y, a2[tm].y, a3[tm].y, b0.x, b1.x);
                }
            }
        }
        __syncthreads();
    }
    // ---- epilogue: per-row partial of sum_j tanh(V+bv)*sigm(U+bu)*Ww
    float part[2][2] = {{0.f, 0.f}, {0.f, 0.f}};
#pragma unroll
    for (int tm = 0; tm < 2; tm++)
#pragma unroll
        for (int tn = 0; tn < 8; tn++) {
            int j = wn * 32 + tn * 4 + (lane & 3);
            float bvj = bv[j], buj = bu[j], wwj = Ww[j];
            part[tm][0] += tanh_fast(c[tm][tn][0] + bvj) * sigm_fast(c[tm][tn][1] + buj) * wwj;
            part[tm][1] += tanh_fast(c[tm][tn][2] + bvj) * sigm_fast(c[tm][tn][3] + buj) * wwj;
        }
#pragma unroll
    for (int tm = 0; tm < 2; tm++)
#pragma unroll
        for (int h = 0; h < 2; h++) {
            part[tm][h] += __shfl_xor_sync(0xffffffffu, part[tm][h], 1);
            part[tm][h] += __shfl_xor_sync(0xffffffffu, part[tm][h], 2);
        }
    if ((lane & 3) == 0) {
#pragma unroll
        for (int tm = 0; tm < 2; tm++)
#pragma unroll
            for (int h = 0; h < 2; h++) {
                int r = wm * 32 + tm * 16 + h * 8 + (lane >> 2);
                red[r][wn] = part[tm][h];
            }
    }
    __syncthreads();
    if (tid < 64)
        g_score[bm + tid] = red[tid][0] + red[tid][1] + red[tid][2] + red[tid][3] + bw[0];
}

// ---------------------------------------------------------------------------
// Stage 3a: per-group softmax stats (max + sum of exp).
// ---------------------------------------------------------------------------
__global__ __launch_bounds__(256) void softmax_stats_k()
{
    __shared__ float red[256];
    const int tid = threadIdx.x;
    const size_t base = (size_t)blockIdx.x * MG;

    float lm = -1e30f;
    for (int i = tid; i < MG; i += 256) lm = fmaxf(lm, g_score[base + i]);
    red[tid] = lm; __syncthreads();
    for (int s = 128; s > 0; s >>= 1) {
        if (tid < s) red[tid] = fmaxf(red[tid], red[tid + s]);
        __syncthreads();
    }
    const float maxv = red[0];
    __syncthreads();

    float ls = 0.f;
    for (int i = tid; i < MG; i += 256) ls += expf(g_score[base + i] - maxv);
    red[tid] = ls; __syncthreads();
    for (int s = 128; s > 0; s >>= 1) {
        if (tid < s) red[tid] += red[tid + s];
        __syncthreads();
    }
    if (tid == 0) { g_gmax[blockIdx.x] = maxv; g_gsum[blockIdx.x] = red[0]; }
}

// ---------------------------------------------------------------------------
// Stage 3b: weighted partial sums of mid (8 chunks of 256 rows per group).
// ---------------------------------------------------------------------------
__global__ __launch_bounds__(512) void weighted_partial_k()
{
    __shared__ float w_s[256];
    const int tid = threadIdx.x;
    const int chunk = blockIdx.x, g = blockIdx.y;
    const size_t base = (size_t)g * MG + chunk * 256;
    const float maxv = g_gmax[g];

    if (tid < 256) w_s[tid] = expf(g_score[base + tid] - maxv);
    __syncthreads();

    float a0 = 0.f, a1 = 0.f, a2 = 0.f, a3 = 0.f;
    const float* mp = g_mid + base * DM + tid;
    for (int i = 0; i < 256; i += 4) {
        a0 += w_s[i + 0] * mp[(size_t)(i + 0) * DM];
        a1 += w_s[i + 1] * mp[(size_t)(i + 1) * DM];
        a2 += w_s[i + 2] * mp[(size_t)(i + 2) * DM];
        a3 += w_s[i + 3] * mp[(size_t)(i + 3) * DM];
    }
    g_afp[(g * 8 + chunk) * DM + tid] = ((a0 + a1) + (a2 + a3));
}

// ---------------------------------------------------------------------------
// Stage 3c: reduce partials -> af.
// ---------------------------------------------------------------------------
__global__ __launch_bounds__(512) void af_reduce_k()
{
    const int g = blockIdx.x, d = threadIdx.x;
    float s = 0.f;
#pragma unroll
    for (int c = 0; c < 8; c++) s += g_afp[(g * 8 + c) * DM + d];
    g_af[g * DM + d] = s / g_gsum[g];
}

// ---------------------------------------------------------------------------
// Stage 4a: per-group gated-attn raw score (64 CTAs, 128 threads).
// ---------------------------------------------------------------------------
__global__ __launch_bounds__(128) void bag_score_k(
    const float* __restrict__ Wv2, const float* __restrict__ bv2,
    const float* __restrict__ Wu2, const float* __restrict__ bu2,
    const float* __restrict__ Ww2, const float* __restrict__ bw2)
{
    __shared__ float afs[DM];
    __shared__ float red[128];
    const int tid = threadIdx.x;
    const int g = blockIdx.x;
    for (int t = tid; t < DM; t += 128) afs[t] = g_af[g * DM + t];
    __syncthreads();

    const int j = tid;
    float sv = 0.f, su = 0.f;
#pragma unroll 4
    for (int d = 0; d < DM; d++) {
        float a = afs[d];
        sv += a * Wv2[d * DA + j];
        su += a * Wu2[d * DA + j];
    }
    float v = tanhf(sv + bv2[j]);
    float u = 1.f / (1.f + expf(-(su + bu2[j])));
    red[tid] = v * u * Ww2[j];
    __syncthreads();
    for (int s = 64; s > 0; s >>= 1) {
        if (tid < s) red[tid] += red[tid + s];
        __syncthreads();
    }
    if (tid == 0) g_a2raw[g] = red[0] + bw2[0];
}

// ---------------------------------------------------------------------------
// Stage 5a: sub_preds_cat (64 CTAs, 128 threads).
// ---------------------------------------------------------------------------
__global__ __launch_bounds__(128) void subpred_k(
    const float* __restrict__ Wsc, const float* __restrict__ bsc,
    float* __restrict__ out)
{
    __shared__ float afs[DM];
    __shared__ float red[128];
    const int tid = threadIdx.x;
    const int gi = blockIdx.x;            // = b*GG + gl
    for (int t = tid; t < DM; t += 128) afs[t] = g_af[gi * DM + t];
    __syncthreads();
    const int c = tid & 1, lane = tid >> 1;   // 64 lanes per class
    float s = 0.f;
    for (int d = lane; d < DM; d += 64) s += afs[d] * Wsc[d * CC + c];
    red[c * 64 + lane] = s;
    __syncthreads();
    for (int st = 32; st > 0; st >>= 1) {
        if (lane < st) red[c * 64 + lane] += red[c * 64 + lane + st];
        __syncthreads();
    }
    if (lane == 0) {
        int b = gi >> 3, gl = gi & 7;
        out[BB * CC + (gl * BB + b) * CC + c] = red[c * 64] + bsc[c];
    }
}

// ---------------------------------------------------------------------------
// Stage 4b+5b: per-bag softmax over groups, bag_feat, bag_pred.
// ---------------------------------------------------------------------------
__global__ __launch_bounds__(256) void bag_final_k(
    const float* __restrict__ Wbc, const float* __restrict__ bbc,
    float* __restrict__ out)
{
    __shared__ float afs[GG][DM];
    __shared__ float w[GG];
    __shared__ float bfs[DM];
    __shared__ float red[256];
    const int tid = threadIdx.x;
    const int b = blockIdx.x;

    for (int t = tid; t < GG * DM; t += 256)
        afs[t >> 9][t & 511] = g_af[(b * GG + (t >> 9)) * DM + (t & 511)];
    if (tid == 0) {
        float a2[GG], mx = -1e30f;
        for (int g = 0; g < GG; g++) { a2[g] = g_a2raw[b * GG + g]; mx = fmaxf(mx, a2[g]); }
        float s = 0.f;
        for (int g = 0; g < GG; g++) { a2[g] = expf(a2[g] - mx); s += a2[g]; }
        for (int g = 0; g < GG; g++) w[g] = a2[g] / s;
    }
    __syncthreads();
    for (int d = tid; d < DM; d += 256) {
        float s = 0.f;
#pragma unroll
        for (int g = 0; g < GG; g++) s += w[g] * afs[g][d];
        bfs[d] = s;
        g_bagfeat[b * DM + d] = s;
        g_xcat[b * DM + d] = s;
    }
    __syncthreads();
    const int c = tid & 1, lane = tid >> 1;   // 128 lanes per class
    float s = 0.f;
    for (int d = lane; d < DM; d += 128) s += bfs[d] * Wbc[d * CC + c];
    red[c * 128 + lane] = s;
    __syncthreads();
    for (int st = 64; st > 0; st >>= 1) {
        if (lane < st) red[c * 128 + lane] += red[c * 128 + lane + st];
        __syncthreads();
    }
    if (lane == 0) out[b * CC + c] = red[c * 128] + bbc[c];
}

// ---------------------------------------------------------------------------
__global__ void copy_reh_k(const float* __restrict__ reh)
{
    int i = blockIdx.x * 256 + threadIdx.x;
    *(float4*)(g_xcat + BB * DM + i * 4) = *(const float4*)(reh + i * 4);
}

// ---------------------------------------------------------------------------
// Stage 6a: _x = leaky_relu(xcat@Wf+bf); xn = _x / (||_x|| + 1e-12).
// ---------------------------------------------------------------------------
__global__ __launch_bounds__(256) void feat_xn_k(
    const float* __restrict__ Wf, const float* __restrict__ bf)
{
    __shared__ float xs[8][DM];
    __shared__ float red[8][260];
    const int tid = threadIdx.x;
    const int r0 = blockIdx.x * 8;

    for (int t = tid; t < 8 * DM; t += 256)
        xs[t >> 9][t & 511] = g_xcat[(r0 + (t >> 9)) * DM + (t & 511)];
    __syncthreads();

    const int j = tid;
    float acc[8];
#pragma unroll
    for (int r = 0; r < 8; r++) acc[r] = 0.f;
    for (int d = 0; d < DM; d++) {
        float w = Wf[d * DH + j];
#pragma unroll
        for (int r = 0; r < 8; r++) acc[r] += xs[r][d] * w;
    }
    float xv[8];
#pragma unroll
    for (int r = 0; r < 8; r++) {
        float v = acc[r] + bf[j];
        xv[r] = v >= 0.f ? v : 0.01f * v;
        red[r][j] = xv[r] * xv[r];
    }
    __syncthreads();
    for (int s = 128; s > 0; s >>= 1) {
        if (j < s) {
#pragma unroll
            for (int r = 0; r < 8; r++) red[r][j] += red[r][j + s];
        }
        __syncthreads();
    }
#pragma unroll
    for (int r = 0; r < 8; r++) {
        float nrm = sqrtf(red[r][0]) + 1e-12f;
        g_xn[(r0 + r) * DH + j] = xv[r] / nrm;
    }
}

// ---------------------------------------------------------------------------
// Stage 6b: sim = xn @ xn^T.
// ---------------------------------------------------------------------------
__global__ __launch_bounds__(256) void sim_k()
{
    __shared__ float Asx[32][129];
    __shared__ float Bsx[32][129];
    const int tid = threadIdx.x, tx = tid & 15, ty = tid >> 4;
    const int rb = blockIdx.y * 32, cb = blockIdx.x * 32;
    float c00 = 0.f, c01 = 0.f, c10 = 0.f, c11 = 0.f;

    for (int kc = 0; kc < DH; kc += 128) {
        for (int t = tid; t < 32 * 128; t += 256) {
            int row = t >> 7, k = t & 127;
            int gr = rb + row, gc = cb + row;
            Asx[row][k] = (gr < NN) ? g_xn[gr * DH + kc + k] : 0.f;
            Bsx[row][k] = (gc < NN) ? g_xn[gc * DH + kc + k] : 0.f;
        }
        __syncthreads();
#pragma unroll 8
        for (int k = 0; k < 128; k++) {
            float a0 = Asx[ty * 2][k],     a1 = Asx[ty * 2 + 1][k];
            float b0 = Bsx[tx * 2][k],     b1 = Bsx[tx * 2 + 1][k];
            c00 += a0 * b0; c01 += a0 * b1;
            c10 += a1 * b0; c11 += a1 * b1;
        }
        __syncthreads();
    }
    int i0 = rb + ty * 2, j0 = cb + tx * 2;
    if (i0 < NN     && j0 < NN)     g_sim[i0 * NN + j0] = c00;
    if (i0 < NN     && j0 + 1 < NN) g_sim[i0 * NN + j0 + 1] = c01;
    if (i0 + 1 < NN && j0 < NN)     g_sim[(i0 + 1) * NN + j0] = c10;
    if (i0 + 1 < NN && j0 + 1 < NN) g_sim[(i0 + 1) * NN + j0 + 1] = c11;
}

// ---------------------------------------------------------------------------
// Stage 6c: top-4 indices per row (ties -> lower index first).
// ---------------------------------------------------------------------------
__global__ __launch_bounds__(256) void topk_k()
{
    const int warp = threadIdx.x >> 5, lane = threadIdx.x & 31;
    const int row = blockIdx.x * 8 + warp;
    const float* sr = g_sim + (size_t)row * NN;
    int sel[4] = {-1, -1, -1, -1};
#pragma unroll
    for (int k = 0; k < 4; k++) {
        float bv = -1e30f; int bi = NN;
        for (int j = lane; j < NN; j += 32) {
            if (j == sel[0] || j == sel[1] || j == sel[2] || j == sel[3]) continue;
            float v = sr[j];
            if (v > bv || (v == bv && j < bi)) { bv = v; bi = j; }
        }
        for (int off = 16; off; off >>= 1) {
            float ov = __shfl_down_sync(0xffffffffu, bv, off);
            int   oi = __shfl_down_sync(0xffffffffu, bi, off);
            if (ov > bv || (ov == bv && oi < bi)) { bv = ov; bi = oi; }
        }
        bi = __shfl_sync(0xffffffffu, bi, 0);
        sel[k] = bi;
    }
    if (lane < 4) g_idx[row * 4 + lane] = sel[lane];
}

// ---------------------------------------------------------------------------
// Stage 6d: gather-means (float4 vectorized).
// ---------------------------------------------------------------------------
__global__ void gather_mean_k(int mode)
{
    int t = blockIdx.x * 256 + threadIdx.x;      // over NN*DM/4
    if (t >= NN * DM / 4) return;
    int i = t >> 7, d4 = (t & 127) * 4;
    const float* src = (mode == 0) ? g_xcat : (mode == 1) ? g_h : g_h1;
    float* dst = (mode == 0) ? g_h : (mode == 1) ? g_m1 : g_m2;
    const int* ip = g_idx + i * 4;
    float4 s0 = *(const float4*)(src + (size_t)ip[0] * DM + d4);
    float4 s1 = *(const float4*)(src + (size_t)ip[1] * DM + d4);
    float4 s2 = *(const float4*)(src + (size_t)ip[2] * DM + d4);
    float4 s3 = *(const float4*)(src + (size_t)ip[3] * DM + d4);
    float4 r;
    r.x = (s0.x + s1.x + s2.x + s3.x) * 0.25f;
    r.y = (s0.y + s1.y + s2.y + s3.y) * 0.25f;
    r.z = (s0.z + s1.z + s2.z + s3.z) * 0.25f;
    r.w = (s0.w + s1.w + s2.w + s3.w) * 0.25f;
    if (mode == 0 && i < BB) {
        float4 bfv = *(const float4*)(g_bagfeat + i * DM + d4);
        r.x += bfv.x; r.y += bfv.y; r.z += bfv.z; r.w += bfv.w;
    }
    *(float4*)(dst + (size_t)i * DM + d4) = r;
}

// ---------------------------------------------------------------------------
// Stage 6e: h1 = relu(m1@Wg1 + h@Wg1s + bg1). f32x2, col-pair per thread.
// ---------------------------------------------------------------------------
__global__ __launch_bounds__(256) void dualgemm_relu_k(
    const float* __restrict__ W1, const float* __restrict__ W2,
    const float* __restrict__ bias)
{
    __shared__ float ms[8][DM];
    __shared__ float hs[8][DM];
    const int tid = threadIdx.x;
    const int r0 = blockIdx.x * 8;
    for (int t = tid; t < 8 * DM; t += 256) {
        int r = t >> 9, d = t & 511;
        ms[r][d] = g_m1[(r0 + r) * DM + d];
        hs[r][d] = g_h[(r0 + r) * DM + d];
    }
    __syncthreads();
    const int j = 2 * tid;
    u64 acc[8];
#pragma unroll
    for (int r = 0; r < 8; r++) acc[r] = 0ull;
#pragma unroll 4
    for (int k = 0; k < DM; k++) {
        u64 wa = *(const u64*)(W1 + (size_t)k * DM + j);
        u64 wb = *(const u64*)(W2 + (size_t)k * DM + j);
#pragma unroll
        for (int r = 0; r < 8; r++) {
            float m = ms[r][k], h = hs[r][k];
            fma2(acc[r], pk2(m, m), wa);
            fma2(acc[r], pk2(h, h), wb);
        }
    }
#pragma unroll
    for (int r = 0; r < 8; r++) {
        float2 f = up2(acc[r]);
        float v0 = f.x + bias[j];
        float v1 = f.y + bias[j + 1];
        g_h1[(r0 + r) * DM + j]     = v0 > 0.f ? v0 : 0.f;
        g_h1[(r0 + r) * DM + j + 1] = v1 > 0.f ? v1 : 0.f;
    }
}

// ---------------------------------------------------------------------------
// Stage 6f: logits_graph = (m2@Wg2 + h1@Wg2s + bg2)[:8]
// ---------------------------------------------------------------------------
__global__ void final_logits_k(
    const float* __restrict__ Wg2, const float* __restrict__ Wg2s,
    const float* __restrict__ bg2, float* __restrict__ out)
{
    int t = threadIdx.x;
    if (t < BB * CC) {
        int i = t >> 1, c = t & 1;
        float s = bg2[c];
        for (int k = 0; k < DM; k++)
            s += g_m2[i * DM + k] * Wg2[k * CC + c]
               + g_h1[i * DM + k] * Wg2s[k * CC + c];
        out[BB * CC + NGROUP * CC + i * CC + c] = s;   // offset 144
    }
}

// ---------------------------------------------------------------------------
extern "C" void kernel_launch(void* const* d_in, const int* in_sizes, int n_in,
                              void* d_out, int out_size)
{
    const float* x    = (const float*)d_in[0];
    const float* reh  = (const float*)d_in[1];
    const float* Wdr  = (const float*)d_in[2];
    const float* bdr  = (const float*)d_in[3];
    const float* Wv1  = (const float*)d_in[4];
    const float* bv1  = (const float*)d_in[5];
    const float* Wu1  = (const float*)d_in[6];
    const float* bu1  = (const float*)d_in[7];
    const float* Ww1  = (const float*)d_in[8];
    const float* bw1  = (const float*)d_in[9];
    const float* Wsc  = (const float*)d_in[10];
    const float* bsc  = (const float*)d_in[11];
    const float* Wv2  = (const float*)d_in[12];
    const float* bv2  = (const float*)d_in[13];
    const float* Wu2  = (const float*)d_in[14];
    const float* bu2  = (const float*)d_in[15];
    const float* Ww2  = (const float*)d_in[16];
    const float* bw2  = (const float*)d_in[17];
    const float* Wbc  = (const float*)d_in[18];
    const float* bbc  = (const float*)d_in[19];
    const float* Wf   = (const float*)d_in[20];
    const float* bf   = (const float*)d_in[21];
    const float* Wg1  = (const float*)d_in[22];
    const float* Wg1s = (const float*)d_in[23];
    const float* bg1  = (const float*)d_in[24];
    const float* Wg2  = (const float*)d_in[25];
    const float* Wg2s = (const float*)d_in[26];
    const float* bg2  = (const float*)d_in[27];
    float* out = (float*)d_out;

    gemm_relu_tc<<<dim3(4, MROWS / 128), 256>>>(x, Wdr, bdr);
    attn_score_tc<<<MROWS / 64, 256>>>(Wv1, bv1, Wu1, bu1, Ww1, bw1);
    softmax_stats_k<<<NGROUP, 256>>>();
    weighted_partial_k<<<dim3(8, NGROUP), 512>>>();
    af_reduce_k<<<NGROUP, 512>>>();
    bag_score_k<<<NGROUP, 128>>>(Wv2, bv2, Wu2, bu2, Ww2, bw2);
    subpred_k<<<NGROUP, 128>>>(Wsc, bsc, out);
    bag_final_k<<<BB, 256>>>(Wbc, bbc, out);
    copy_reh_k<<<(BUFN * DM / 4) / 256, 256>>>(reh);
    feat_xn_k<<<NN / 8, 256>>>(Wf, bf);
    sim_k<<<dim3(33, 33), 256>>>();
    topk_k<<<NN / 8, 256>>>();
    gather_mean_k<<<(NN * DM / 4 + 255) / 256, 256>>>(0);
    gather_mean_k<<<(NN * DM / 4 + 255) / 256, 256>>>(1);
    dualgemm_relu_k<<<NN / 8, 256>>>(Wg1, Wg1s, bg1);
    gather_mean_k<<<(NN * DM / 4 + 255) / 256, 256>>>(2);
    final_logits_k<<<1, 32>>>(Wg2, Wg2s, bg2, out);
}